// round 1
// baseline (speedup 1.0000x reference)
#include <cuda_runtime.h>

// Problem constants (fixed by the reference).
#define C_OUT   96
#define NK      11
#define C_IN    1056      // C_OUT * NK
#define GB      8         // batch
#define HOUT    56
#define WOUT    56
#define HIN     60        // HOUT + 2*EP
#define EP      2
#define PLANE   (HIN*HIN)         // 3600
#define NPIX    (HOUT*WOUT)       // 3136
#define NTERM   44                // NK * G  (G = 4)
#define THREADS 448               // 8 rows * 56 cols
#define PPT     7                 // pixels per thread (3136 / 448)
#define OUT_PLANE ((size_t)GB*C_OUT*HOUT*WOUT)   // 2408448

// Dynamic smem layout:
//   [0, 11*PLANE)                : 11 input planes (floats)
//   then tables: s_h, b_h (int), w_h (float), s_v, b_v, w_v, b_i, w_i
#define SM_PLANES   (NK*PLANE)               // 39600 floats
#define SM_TABLES   (NTERM*6 + 8)            // words
#define SMEM_BYTES  ((SM_PLANES + SM_TABLES) * 4)

__global__ __launch_bounds__(THREADS, 1)
void addshift_kernel(const float* __restrict__ x,
                     const float* __restrict__ w1,
                     const float* __restrict__ w2,
                     const float* __restrict__ w3,
                     const int*   __restrict__ pad_hv,
                     const int*   __restrict__ idx_identit,
                     float* __restrict__ out)
{
    extern __shared__ float smem[];
    float* planes = smem;
    int*   s_h = (int*)  (smem + SM_PLANES);
    int*   b_h = (int*)  (smem + SM_PLANES + NTERM);
    float* w_h =         (smem + SM_PLANES + 2*NTERM);
    int*   s_v = (int*)  (smem + SM_PLANES + 3*NTERM);
    int*   b_v = (int*)  (smem + SM_PLANES + 4*NTERM);
    float* w_v =         (smem + SM_PLANES + 5*NTERM);
    int*   b_i = (int*)  (smem + SM_PLANES + 6*NTERM);
    float* w_i =         (smem + SM_PLANES + 6*NTERM + 4);

    const int tid = threadIdx.x;
    const int co  = blockIdx.x;   // 0..95
    const int b   = blockIdx.y;   // 0..7
    const int c0  = co * NK;

    // ---- init tables ----
    if (tid < NTERM) {
        int nk = tid >> 2;
        int g  = tid & 3;
        int c  = c0 + nk;
        s_h[tid] = pad_hv[c*8 + g];
        b_h[tid] = nk * PLANE;
        w_h[tid] = w1[g*C_IN + c];
        s_v[tid] = pad_hv[c*8 + 4 + g];
        b_v[tid] = nk * PLANE;
        w_v[tid] = w2[g*C_IN + c];
    }
    if (tid >= 64 && tid < 68) {
        int g = tid - 64;
        int c = idx_identit[co*4 + g];
        b_i[g] = (c - c0) * PLANE;
        w_i[g] = w3[g*C_OUT + co];
    }

    // ---- load 11 contiguous planes (158.4 KB) with float4 ----
    {
        const float4* src = (const float4*)(x + (size_t)(b*C_IN + c0) * PLANE);
        float4* dst = (float4*)planes;
        #pragma unroll 4
        for (int i = tid; i < SM_PLANES/4; i += THREADS)
            dst[i] = src[i];
    }
    __syncthreads();

    // ---- pixel mapping: w fixed per thread, h = h0 + 8k ----
    const int w  = tid % WOUT;          // 0..55
    const int h0 = tid / WOUT;          // 0..7
    const int col = w + EP;             // 2..57
    const int rb0 = (h0 + EP) * HIN;    // row base for k=0

    float acc_h[PPT], acc_v[PPT], acc_i[PPT];
    #pragma unroll
    for (int k = 0; k < PPT; k++) { acc_h[k] = 0.f; acc_v[k] = 0.f; acc_i[k] = 0.f; }

    // ---- horizontal shifts: bounds check independent of k ----
    #pragma unroll 4
    for (int t = 0; t < NTERM; t++) {
        int iw = col + s_h[t];
        if ((unsigned)iw < (unsigned)HIN) {
            const float* p = planes + b_h[t] + iw + rb0;
            float wt = w_h[t];
            #pragma unroll
            for (int k = 0; k < PPT; k++)
                acc_h[k] = fmaf(p[k * 8 * HIN], wt, acc_h[k]);
        }
    }

    // ---- vertical shifts: bounds check per k ----
    #pragma unroll 4
    for (int t = 0; t < NTERM; t++) {
        int ihb = h0 + EP + s_v[t];
        const float* p = planes + b_v[t] + col;
        float wt = w_v[t];
        #pragma unroll
        for (int k = 0; k < PPT; k++) {
            int ih = ihb + 8 * k;
            if ((unsigned)ih < (unsigned)HIN)
                acc_v[k] = fmaf(p[ih * HIN], wt, acc_v[k]);
        }
    }

    // ---- identity ----
    #pragma unroll
    for (int g = 0; g < 4; g++) {
        const float* p = planes + b_i[g] + rb0 + col;
        float wt = w_i[g];
        #pragma unroll
        for (int k = 0; k < PPT; k++)
            acc_i[k] = fmaf(p[k * 8 * HIN], wt, acc_i[k]);
    }

    // ---- write outputs (coalesced: consecutive tid -> consecutive w) ----
    float* oh = out;
    float* ov = out + OUT_PLANE;
    float* oi = out + 2 * OUT_PLANE;
    const size_t base = ((size_t)(b * C_OUT + co)) * NPIX;
    #pragma unroll
    for (int k = 0; k < PPT; k++) {
        size_t idx = base + (size_t)(h0 + 8*k) * WOUT + w;
        oh[idx] = acc_h[k];
        ov[idx] = acc_v[k];
        oi[idx] = acc_i[k];
    }
}

extern "C" void kernel_launch(void* const* d_in, const int* in_sizes, int n_in,
                              void* d_out, int out_size)
{
    const float* x           = (const float*)d_in[0];
    const float* w1          = (const float*)d_in[1];
    const float* w2          = (const float*)d_in[2];
    const float* w3          = (const float*)d_in[3];
    const int*   pad_hv      = (const int*)  d_in[4];
    const int*   idx_identit = (const int*)  d_in[5];
    float*       out         = (float*)d_out;

    cudaFuncSetAttribute(addshift_kernel,
                         cudaFuncAttributeMaxDynamicSharedMemorySize, SMEM_BYTES);

    dim3 grid(C_OUT, GB);
    addshift_kernel<<<grid, THREADS, SMEM_BYTES>>>(x, w1, w2, w3, pad_hv,
                                                   idx_identit, out);
}

// round 2
// speedup vs baseline: 1.1511x; 1.1511x over previous
#include <cuda_runtime.h>

// Problem constants (fixed by the reference).
#define C_OUT   96
#define NK      11
#define C_IN    1056      // C_OUT * NK
#define GB      8         // batch
#define HOUT    56
#define WOUT    56
#define HIN     60        // HOUT + 2*EP
#define EP      2
#define PLANE   (HIN*HIN)         // 3600
#define NPIX    (HOUT*WOUT)       // 3136
#define NTERM   44                // NK * G  (G = 4)
#define THREADS 896               // 16 rows * 56 cols -> 28 warps
#define OUT_PLANE ((size_t)GB*C_OUT*HOUT*WOUT)   // 2408448

// Dynamic smem layout: 11 planes, then tables s_h, w_h, s_v, w_v, b_i, w_i
#define SM_PLANES   (NK*PLANE)               // 39600 floats
#define SM_TABLES   (NTERM*4 + 8)
#define SMEM_BYTES  ((SM_PLANES + SM_TABLES) * 4)

#define ROWSTEP     (16*HIN)                 // 960 : +16 output rows

__global__ __launch_bounds__(THREADS, 1)
void addshift_kernel(const float* __restrict__ x,
                     const float* __restrict__ w1,
                     const float* __restrict__ w2,
                     const float* __restrict__ w3,
                     const int*   __restrict__ pad_hv,
                     const int*   __restrict__ idx_identit,
                     float* __restrict__ out)
{
    extern __shared__ float smem[];
    float* planes = smem;
    int*   s_h = (int*)  (smem + SM_PLANES);
    float* w_h =         (smem + SM_PLANES + NTERM);
    int*   s_v = (int*)  (smem + SM_PLANES + 2*NTERM);
    float* w_v =         (smem + SM_PLANES + 3*NTERM);
    int*   b_i = (int*)  (smem + SM_PLANES + 4*NTERM);
    float* w_i =         (smem + SM_PLANES + 4*NTERM + 4);

    const int tid = threadIdx.x;
    const int co  = blockIdx.x;   // 0..95
    const int b   = blockIdx.y;   // 0..7
    const int c0  = co * NK;

    // ---- init tables ----
    if (tid < NTERM) {
        int nk = tid >> 2;
        int g  = tid & 3;
        int c  = c0 + nk;
        s_h[tid] = pad_hv[c*8 + g];
        w_h[tid] = w1[g*C_IN + c];
        s_v[tid] = pad_hv[c*8 + 4 + g];
        w_v[tid] = w2[g*C_IN + c];
    }
    if (tid >= 64 && tid < 68) {
        int g = tid - 64;
        int c = idx_identit[co*4 + g];
        b_i[g] = (c - c0) * PLANE;
        w_i[g] = w3[g*C_OUT + co];
    }

    // ---- load 11 contiguous planes (158.4 KB) with float4 ----
    {
        const float4* src = (const float4*)(x + (size_t)(b*C_IN + c0) * PLANE);
        float4* dst = (float4*)planes;
        #pragma unroll
        for (int i = tid; i < SM_PLANES/4; i += THREADS)
            dst[i] = src[i];
    }
    __syncthreads();

    // ---- pixel mapping: w fixed per thread, h = h0 + 16k, k = 0..3 ----
    const int w   = tid % WOUT;         // 0..55
    const int h0  = tid / WOUT;         // 0..15
    const int col = w + EP;             // 2..57
    const int rb0 = (h0 + EP) * HIN;    // smem row base for k=0
    const bool k3 = (h0 < 8);           // k=3 (h = h0+48) valid only for h0<8
    const int off3 = k3 ? 3*ROWSTEP : 0;  // safe in-bounds offset when k3 invalid

    float acc_h[4] = {0.f, 0.f, 0.f, 0.f};
    float acc_v[4] = {0.f, 0.f, 0.f, 0.f};
    float acc_i[4] = {0.f, 0.f, 0.f, 0.f};

    // ---- horizontal shifts: clamp index, zero weight when OOB (branch-free) ----
    #pragma unroll 4
    for (int t = 0; t < NTERM; t++) {
        int s  = s_h[t];
        int iw = col + s;
        bool valid = (unsigned)iw < (unsigned)HIN;
        int iwc = min(max(iw, 0), HIN-1);
        float wt = valid ? w_h[t] : 0.0f;
        const float* p = planes + (t >> 2) * PLANE + rb0 + iwc;
        acc_h[0] = fmaf(p[0],         wt, acc_h[0]);
        acc_h[1] = fmaf(p[ROWSTEP],   wt, acc_h[1]);
        acc_h[2] = fmaf(p[2*ROWSTEP], wt, acc_h[2]);
        acc_h[3] = fmaf(p[off3],      wt, acc_h[3]);  // garbage if !k3 (unstored)
    }

    // ---- vertical shifts: per-k row-bound predicate ----
    const int vrow0 = h0 + EP;          // logical row for k=0 before shift
    #pragma unroll 4
    for (int t = 0; t < NTERM; t++) {
        int s   = s_v[t];
        float wt = w_v[t];
        int ihb = vrow0 + s;
        const float* p = planes + (t >> 2) * PLANE + col + ihb * HIN;
        #pragma unroll
        for (int k = 0; k < 4; k++) {
            int ih = ihb + 16*k;
            if ((unsigned)ih < (unsigned)HIN)
                acc_v[k] = fmaf(p[k*ROWSTEP], wt, acc_v[k]);
        }
    }

    // ---- identity ----
    #pragma unroll
    for (int g = 0; g < 4; g++) {
        const float* p = planes + b_i[g] + rb0 + col;
        float wt = w_i[g];
        acc_i[0] = fmaf(p[0],         wt, acc_i[0]);
        acc_i[1] = fmaf(p[ROWSTEP],   wt, acc_i[1]);
        acc_i[2] = fmaf(p[2*ROWSTEP], wt, acc_i[2]);
        acc_i[3] = fmaf(p[off3],      wt, acc_i[3]);
    }

    // ---- write outputs (coalesced: consecutive tid -> consecutive w) ----
    float* oh = out;
    float* ov = out + OUT_PLANE;
    float* oi = out + 2 * OUT_PLANE;
    const size_t base = ((size_t)(b * C_OUT + co)) * NPIX + (size_t)h0 * WOUT + w;
    #pragma unroll
    for (int k = 0; k < 3; k++) {
        size_t idx = base + (size_t)(16*k) * WOUT;
        oh[idx] = acc_h[k];
        ov[idx] = acc_v[k];
        oi[idx] = acc_i[k];
    }
    if (k3) {
        size_t idx = base + (size_t)48 * WOUT;
        oh[idx] = acc_h[3];
        ov[idx] = acc_v[3];
        oi[idx] = acc_i[3];
    }
}

extern "C" void kernel_launch(void* const* d_in, const int* in_sizes, int n_in,
                              void* d_out, int out_size)
{
    const float* x           = (const float*)d_in[0];
    const float* w1          = (const float*)d_in[1];
    const float* w2          = (const float*)d_in[2];
    const float* w3          = (const float*)d_in[3];
    const int*   pad_hv      = (const int*)  d_in[4];
    const int*   idx_identit = (const int*)  d_in[5];
    float*       out         = (float*)d_out;

    cudaFuncSetAttribute(addshift_kernel,
                         cudaFuncAttributeMaxDynamicSharedMemorySize, SMEM_BYTES);

    dim3 grid(C_OUT, GB);
    addshift_kernel<<<grid, THREADS, SMEM_BYTES>>>(x, w1, w2, w3, pad_hv,
                                                   idx_identit, out);
}

// round 3
// speedup vs baseline: 1.2132x; 1.0539x over previous
#include <cuda_runtime.h>

// Problem constants (fixed by the reference).
#define C_OUT   96
#define NK      11
#define C_IN    1056      // C_OUT * NK
#define GB      8         // batch
#define HOUT    56
#define WOUT    56
#define HIN     60        // HOUT + 2*EP
#define EP      2
#define PLANE   (HIN*HIN)         // 3600
#define NPIX    (HOUT*WOUT)       // 3136
#define NTERM   44                // NK * G  (G = 4)
#define THREADS 896               // 16 rows * 56 cols -> 28 warps
#define OUT_PLANE ((size_t)GB*C_OUT*HOUT*WOUT)   // 2408448

// Dynamic smem layout: 11 planes, then fused table (NTERM float4) + id tables
#define SM_PLANES   (NK*PLANE)               // 39600 floats
#define SM_TAB      SM_PLANES                // float4-aligned? 39600*4 B = 158400, %16 == 0 ✓
#define SM_TABLES   (NTERM*4 + 8)
#define SMEM_BYTES  ((SM_PLANES + SM_TABLES) * 4)

#define ROWSTEP     (16*HIN)                 // 960 : +16 output rows

__global__ __launch_bounds__(THREADS, 1)
void addshift_kernel(const float* __restrict__ x,
                     const float* __restrict__ w1,
                     const float* __restrict__ w2,
                     const float* __restrict__ w3,
                     const int*   __restrict__ pad_hv,
                     const int*   __restrict__ idx_identit,
                     float* __restrict__ out)
{
    extern __shared__ float smem[];
    float* planes = smem;
    // fused term table: tab[t] = {as_int(s_h), w_h, as_int(s_v), w_v}
    float4* tab   = (float4*)(smem + SM_TAB);
    int*    b_i   = (int*)  (smem + SM_TAB + 4*NTERM);
    float*  w_i   =         (smem + SM_TAB + 4*NTERM + 4);

    const int tid = threadIdx.x;
    const int co  = blockIdx.x;   // 0..95
    const int b   = blockIdx.y;   // 0..7
    const int c0  = co * NK;

    // ---- init tables ----
    if (tid < NTERM) {
        int nk = tid >> 2;
        int g  = tid & 3;
        int c  = c0 + nk;
        float4 e;
        e.x = __int_as_float(pad_hv[c*8 + g]);        // s_h
        e.y = w1[g*C_IN + c];                          // w_h
        e.z = __int_as_float(pad_hv[c*8 + 4 + g]);     // s_v
        e.w = w2[g*C_IN + c];                          // w_v
        tab[tid] = e;
    }
    if (tid >= 64 && tid < 68) {
        int g = tid - 64;
        int c = idx_identit[co*4 + g];
        b_i[g] = (c - c0) * PLANE;
        w_i[g] = w3[g*C_OUT + co];
    }

    // ---- load 11 contiguous planes (158.4 KB) with float4 ----
    {
        const float4* src = (const float4*)(x + (size_t)(b*C_IN + c0) * PLANE);
        float4* dst = (float4*)planes;
        #pragma unroll
        for (int i = tid; i < SM_PLANES/4; i += THREADS)
            dst[i] = src[i];
    }
    __syncthreads();

    // ---- pixel mapping: w fixed per thread, h = h0 + 16k, k = 0..3 ----
    const int w   = tid % WOUT;         // 0..55
    const int h0  = tid / WOUT;         // 0..15
    const int col = w + EP;             // 2..57
    const int rb0 = (h0 + EP) * HIN;    // smem row base for k=0
    const bool k3 = (h0 < 8);           // k=3 (h = h0+48) valid only for h0<8
    const int off3 = k3 ? 3*ROWSTEP : 0;  // safe in-bounds offset when k3 invalid
    const int vrow0 = h0 + EP;          // logical row for k=0 before v-shift

    const float* base_h = planes + rb0;        // + s-clamped col added per term
    const float* base_v = planes + col;        // + row*HIN added per term

    float acc_h[4] = {0.f, 0.f, 0.f, 0.f};
    float acc_v[4] = {0.f, 0.f, 0.f, 0.f};
    float acc_i[4] = {0.f, 0.f, 0.f, 0.f};

    // ---- fused h+v loop: one LDS.128 table broadcast per term ----
    #pragma unroll
    for (int t = 0; t < NTERM; t++) {
        const int pbase = (t >> 2) * PLANE;   // compile-time constant per iter
        float4 e = tab[t];
        int   sh = __float_as_int(e.x);
        float wh = e.y;
        int   sv = __float_as_int(e.z);
        float wv = e.w;

        // --- horizontal term: clamp index, zero weight when OOB (branch-free)
        {
            int iw = col + sh;
            bool valid = (unsigned)iw < (unsigned)HIN;
            int iwc = min(max(iw, 0), HIN-1);
            float wt = valid ? wh : 0.0f;
            const float* p = base_h + pbase + iwc;
            acc_h[0] = fmaf(p[0],         wt, acc_h[0]);
            acc_h[1] = fmaf(p[ROWSTEP],   wt, acc_h[1]);
            acc_h[2] = fmaf(p[2*ROWSTEP], wt, acc_h[2]);
            acc_h[3] = fmaf(p[off3],      wt, acc_h[3]);  // garbage if !k3 (unstored)
        }

        // --- vertical term: per-k row-bound predicate
        {
            int ihb = vrow0 + sv;
            const float* p = base_v + pbase + ihb * HIN;
            #pragma unroll
            for (int k = 0; k < 4; k++) {
                int ih = ihb + 16*k;
                if ((unsigned)ih < (unsigned)HIN)
                    acc_v[k] = fmaf(p[k*ROWSTEP], wv, acc_v[k]);
            }
        }
    }

    // ---- identity ----
    #pragma unroll
    for (int g = 0; g < 4; g++) {
        const float* p = base_h + b_i[g] + col;
        float wt = w_i[g];
        acc_i[0] = fmaf(p[0],         wt, acc_i[0]);
        acc_i[1] = fmaf(p[ROWSTEP],   wt, acc_i[1]);
        acc_i[2] = fmaf(p[2*ROWSTEP], wt, acc_i[2]);
        acc_i[3] = fmaf(p[off3],      wt, acc_i[3]);
    }

    // ---- write outputs (coalesced: consecutive tid -> consecutive w) ----
    float* oh = out;
    float* ov = out + OUT_PLANE;
    float* oi = out + 2 * OUT_PLANE;
    const size_t base = ((size_t)(b * C_OUT + co)) * NPIX + (size_t)h0 * WOUT + w;
    #pragma unroll
    for (int k = 0; k < 3; k++) {
        size_t idx = base + (size_t)(16*k) * WOUT;
        oh[idx] = acc_h[k];
        ov[idx] = acc_v[k];
        oi[idx] = acc_i[k];
    }
    if (k3) {
        size_t idx = base + (size_t)48 * WOUT;
        oh[idx] = acc_h[3];
        ov[idx] = acc_v[3];
        oi[idx] = acc_i[3];
    }
}

extern "C" void kernel_launch(void* const* d_in, const int* in_sizes, int n_in,
                              void* d_out, int out_size)
{
    const float* x           = (const float*)d_in[0];
    const float* w1          = (const float*)d_in[1];
    const float* w2          = (const float*)d_in[2];
    const float* w3          = (const float*)d_in[3];
    const int*   pad_hv      = (const int*)  d_in[4];
    const int*   idx_identit = (const int*)  d_in[5];
    float*       out         = (float*)d_out;

    cudaFuncSetAttribute(addshift_kernel,
                         cudaFuncAttributeMaxDynamicSharedMemorySize, SMEM_BYTES);

    dim3 grid(C_OUT, GB);
    addshift_kernel<<<grid, THREADS, SMEM_BYTES>>>(x, w1, w2, w3, pad_hv,
                                                   idx_identit, out);
}

// round 5
// speedup vs baseline: 1.2178x; 1.0038x over previous
#include <cuda_runtime.h>
#include <cstdint>

// Problem constants (fixed by the reference).
#define C_OUT   96
#define NK      11
#define C_IN    1056
#define GB      8
#define NTILES  (C_OUT*GB)         // 768 tiles, one per (b, c_out)
#define HOUT    56
#define WOUT    56
#define HIN     60
#define EP      2
#define PLANE   3600
#define PLANE_BYTES 14400
#define NPIX    3136
#define THREADS 896                // 16 rows * 56 cols -> 28 warps
#define OUT_PLANE ((size_t)GB*C_OUT*NPIX)
#define ROWSTEP 960                // 16*HIN

// Plane ring with shared inter-slot zero guards.
// v-row index in [-27, 86] -> offsets [-1618, +5217] from plane start;
// guard of 1620 floats each side (shared between adjacent slots) absorbs all.
#define NSLOT       10
#define GUARD       1620
#define SLOT_STRIDE (PLANE + GUARD)                 // 5220
#define SM_DATA     (NSLOT*SLOT_STRIDE + GUARD)     // 53820 floats
#define OFF_TAB     SM_DATA                          // 44 * float4
#define OFF_WID     (OFF_TAB + 176)                  // 11 floats (+1 pad)
#define OFF_Q       (OFF_TAB + 188)                  // 4 ints (tile queue)
#define OFF_BAR     (OFF_TAB + 192)                  // 10 x u64 mbarriers
#define SMEM_FLOATS (OFF_BAR + 20)
#define SMEM_BYTES  (SMEM_FLOATS * 4)                // ~216 KB

__device__ int g_tile_ctr;

__global__ void reset_kernel() { g_tile_ctr = 0; }

__device__ __forceinline__ uint32_t smem_u32(const void* p) {
    uint32_t a;
    asm("{ .reg .u64 t; cvta.to.shared.u64 t, %1; cvt.u32.u64 %0, t; }"
        : "=r"(a) : "l"(p));
    return a;
}

__device__ __forceinline__ void mbar_init(uint32_t mbar, uint32_t cnt) {
    asm volatile("mbarrier.init.shared.b64 [%0], %1;" :: "r"(mbar), "r"(cnt) : "memory");
}

__device__ __forceinline__ void mbar_wait(uint32_t mbar, int parity) {
    asm volatile(
        "{\n\t.reg .pred P;\n"
        "W_%=:\n\t"
        "mbarrier.try_wait.parity.acquire.cta.shared::cta.b64 P, [%0], %1, 0x989680;\n\t"
        "@P bra D_%=;\n\t"
        "bra W_%=;\n"
        "D_%=:\n\t}"
        :: "r"(mbar), "r"(parity) : "memory");
}

// tid0-only: issue the next plane prefetch in the stream (or sentinel arrive).
__device__ __forceinline__ void issue_one(const float* __restrict__ x, int* q,
                                          uint32_t bar0, uint32_t smem_base,
                                          int& pslot, int& pnk, int& ptq, bool& pdone)
{
    if (pdone) return;
    if (pnk == 0) {
        int t = atomicAdd(&g_tile_ctr, 1);
        q[ptq & 3] = (t < NTILES) ? t : -1;
    }
    int t = q[ptq & 3];
    uint32_t bar = bar0 + 8u * pslot;
    if (t < 0) {
        asm volatile("mbarrier.arrive.shared.b64 _, [%0];" :: "r"(bar) : "memory");
        pdone = true;
    } else {
        uint32_t dst = smem_base + (uint32_t)(GUARD + pslot * SLOT_STRIDE) * 4u;
        const float* src = x + (size_t)((t / C_OUT) * C_IN + (t % C_OUT) * NK + pnk) * PLANE;
        asm volatile("mbarrier.arrive.expect_tx.shared.b64 _, [%0], %1;"
                     :: "r"(bar), "r"((uint32_t)PLANE_BYTES) : "memory");
        asm volatile("cp.async.bulk.shared::cta.global.mbarrier::complete_tx::bytes "
                     "[%0], [%1], %2, [%3];"
                     :: "r"(dst), "l"(src), "r"((uint32_t)PLANE_BYTES), "r"(bar) : "memory");
    }
    pslot = (pslot + 1 == NSLOT) ? 0 : pslot + 1;
    if (++pnk == NK) { pnk = 0; ptq++; }
}

__global__ __launch_bounds__(THREADS, 1)
void addshift_kernel(const float* __restrict__ x,
                     const float* __restrict__ w1,
                     const float* __restrict__ w2,
                     const float* __restrict__ w3,
                     const int*   __restrict__ pad_hv,
                     const int*   __restrict__ idx_identit,
                     float* __restrict__ out)
{
    extern __shared__ float smem[];
    float4* tab = (float4*)(smem + OFF_TAB);
    float*  wid = smem + OFF_WID;
    int*    q   = (int*)(smem + OFF_Q);

    const int tid = threadIdx.x;
    const uint32_t smem_base = smem_u32(smem);
    const uint32_t bar0 = smem_base + (uint32_t)OFF_BAR * 4u;

    // Zero entire data region once (guards stay zero forever; planes overwritten by copies).
    {
        float4* d = (float4*)smem;
        const float4 z = make_float4(0.f, 0.f, 0.f, 0.f);
        for (int i = tid; i < SM_DATA / 4; i += THREADS) d[i] = z;
    }
    if (tid == 0)
        for (int s = 0; s < NSLOT; s++) mbar_init(bar0 + 8u * s, 1);
    __syncthreads();

    // tid0 prefetch state + initial ring fill.
    int pslot = 0, pnk = 0, ptq = 0; bool pdone = false;
    if (tid == 0) {
        asm volatile("fence.proxy.async.shared::cta;" ::: "memory");
        for (int s = 0; s < NSLOT; s++)
            issue_one(x, q, bar0, smem_base, pslot, pnk, ptq, pdone);
    }

    // Per-thread pixel mapping: w fixed, h = h0 + 16k.
    const int w   = tid % WOUT;
    const int h0  = tid / WOUT;
    const int col = w + EP;
    const int rb0 = (h0 + EP) * HIN;
    const int vrow0 = h0 + EP;
    const bool k3 = (h0 < 8);

    int p = 0, tq = 0;   // consumed plane / tile counters
    for (;;) {
        // Wait plane 0 of next tile -> tile id becomes visible (release/acquire via mbarrier).
        mbar_wait(bar0 + 8u * (p % NSLOT), (p / NSLOT) & 1);
        const int t = q[tq & 3];
        if (t < 0) break;
        const int co = t % C_OUT, b = t / C_OUT, c0 = co * NK;

        // Load this tile's term tables.
        if (tid < 44) {
            int nk = tid >> 2, g = tid & 3, c = c0 + nk;
            float4 e;
            e.x = __int_as_float(pad_hv[c*8 + g]);
            e.y = w1[g*C_IN + c];
            e.z = __int_as_float(pad_hv[c*8 + 4 + g]);
            e.w = w2[g*C_IN + c];
            tab[tid] = e;
        }
        if (tid >= 64 && tid < 64 + NK) {
            int nk = tid - 64;
            float s = 0.f;
            #pragma unroll
            for (int g = 0; g < 4; g++)
                if (idx_identit[co*4 + g] - c0 == nk) s += w3[g*C_OUT + co];
            wid[nk] = s;
        }
        __syncthreads();

        float acc_h[4] = {0.f,0.f,0.f,0.f};
        float acc_v[4] = {0.f,0.f,0.f,0.f};
        float acc_i[4] = {0.f,0.f,0.f,0.f};

        for (int nk = 0; nk < NK; nk++) {
            if (nk) mbar_wait(bar0 + 8u * (p % NSLOT), (p / NSLOT) & 1);
            const float* base = smem + GUARD + (p % NSLOT) * SLOT_STRIDE;
            const float* bh = base + rb0;
            const float* bv = base + col;

            #pragma unroll
            for (int g = 0; g < 4; g++) {
                float4 e = tab[nk*4 + g];
                int   sh = __float_as_int(e.x);
                float wh = e.y;
                int   sv = __float_as_int(e.z);
                float wv = e.w;

                int iw = col + sh;
                float wt = ((unsigned)iw < (unsigned)HIN) ? wh : 0.0f;
                const float* ph = bh + iw;                 // guards keep address safe
                acc_h[0] = fmaf(ph[0],         wt, acc_h[0]);
                acc_h[1] = fmaf(ph[ROWSTEP],   wt, acc_h[1]);
                acc_h[2] = fmaf(ph[2*ROWSTEP], wt, acc_h[2]);
                acc_h[3] = fmaf(ph[3*ROWSTEP], wt, acc_h[3]);   // k3 garbage unstored

                const float* pv = bv + (vrow0 + sv) * HIN; // OOB rows hit this slot's zero guards
                acc_v[0] = fmaf(pv[0],         wv, acc_v[0]);
                acc_v[1] = fmaf(pv[ROWSTEP],   wv, acc_v[1]);
                acc_v[2] = fmaf(pv[2*ROWSTEP], wv, acc_v[2]);
                acc_v[3] = fmaf(pv[3*ROWSTEP], wv, acc_v[3]);
            }

            float wi = wid[nk];
            if (wi != 0.0f) {      // warp-uniform
                const float* pi = bh + col;
                acc_i[0] = fmaf(pi[0],         wi, acc_i[0]);
                acc_i[1] = fmaf(pi[ROWSTEP],   wi, acc_i[1]);
                acc_i[2] = fmaf(pi[2*ROWSTEP], wi, acc_i[2]);
                acc_i[3] = fmaf(pi[3*ROWSTEP], wi, acc_i[3]);
            }

            __syncthreads();                  // all warps done with this slot
            if (tid == 0)                     // recycle it for plane p+NSLOT
                issue_one(x, q, bar0, smem_base, pslot, pnk, ptq, pdone);
            p++;
        }

        // Write outputs (coalesced).
        float* oh = out;
        float* ov = out + OUT_PLANE;
        float* oi = out + 2*OUT_PLANE;
        const size_t obase = ((size_t)(b * C_OUT + co)) * NPIX + (size_t)h0 * WOUT + w;
        #pragma unroll
        for (int k = 0; k < 3; k++) {
            size_t idx = obase + (size_t)(16*k) * WOUT;
            oh[idx] = acc_h[k];
            ov[idx] = acc_v[k];
            oi[idx] = acc_i[k];
        }
        if (k3) {
            size_t idx = obase + (size_t)48 * WOUT;
            oh[idx] = acc_h[3];
            ov[idx] = acc_v[3];
            oi[idx] = acc_i[3];
        }
        tq++;
    }
}

extern "C" void kernel_launch(void* const* d_in, const int* in_sizes, int n_in,
                              void* d_out, int out_size)
{
    const float* x           = (const float*)d_in[0];
    const float* w1          = (const float*)d_in[1];
    const float* w2          = (const float*)d_in[2];
    const float* w3          = (const float*)d_in[3];
    const int*   pad_hv      = (const int*)  d_in[4];
    const int*   idx_identit = (const int*)  d_in[5];
    float*       out         = (float*)d_out;

    cudaFuncSetAttribute(addshift_kernel,
                         cudaFuncAttributeMaxDynamicSharedMemorySize, SMEM_BYTES);

    reset_kernel<<<1, 32>>>();
    addshift_kernel<<<148, THREADS, SMEM_BYTES>>>(x, w1, w2, w3, pad_hv,
                                                  idx_identit, out);
}

// round 6
// speedup vs baseline: 1.4019x; 1.1512x over previous
#include <cuda_runtime.h>
#include <cstdint>

// Problem constants (fixed by the reference).
#define C_OUT   96
#define NK      11
#define C_IN    1056
#define GB      8
#define NTILES  (C_OUT*GB)         // 768 tiles, one per (b, c_out)
#define HOUT    56
#define WOUT    56
#define HIN     60
#define EP      2
#define PLANE   3600
#define PLANE_BYTES 14400
#define NPIX    3136
#define NCW     28                 // compute warps
#define THREADS (NCW*32 + 32)      // 928: 28 compute warps + 1 producer warp
#define OUT_PLANE ((size_t)GB*C_OUT*NPIX)
#define ROWSTEP 960                // 16*HIN

// Plane ring with shared inter-slot zero guards.
// v-row index in [-27, 86] -> offsets [-1618, +5217] from plane start;
// 1620-float guards (shared between adjacent slots) absorb all OOB reads.
#define NSLOT       10
#define GUARD       1620
#define SLOT_STRIDE (PLANE + GUARD)                 // 5220
#define SM_DATA     (NSLOT*SLOT_STRIDE + GUARD)     // 53820 floats
#define OFF_TAB     SM_DATA                          // 2 x 44 float4 (double buffer)
#define OFF_WID     (OFF_TAB + 352)                  // 2 x 12 floats
#define OFF_Q       (OFF_WID + 24)                   // 4 ints (tile queue)
#define OFF_BAR     (OFF_Q + 4)                      // 10 full + 10 empty u64
#define SMEM_FLOATS (OFF_BAR + 40)
#define SMEM_BYTES  (SMEM_FLOATS * 4)                // ~217 KB

__device__ int g_tile_ctr;
__global__ void reset_kernel() { g_tile_ctr = 0; }

__device__ __forceinline__ uint32_t smem_u32(const void* p) {
    uint32_t a;
    asm("{ .reg .u64 t; cvta.to.shared.u64 t, %1; cvt.u32.u64 %0, t; }"
        : "=r"(a) : "l"(p));
    return a;
}
__device__ __forceinline__ void mbar_init(uint32_t mbar, uint32_t cnt) {
    asm volatile("mbarrier.init.shared.b64 [%0], %1;" :: "r"(mbar), "r"(cnt) : "memory");
}
__device__ __forceinline__ void mbar_wait(uint32_t mbar, int parity) {
    asm volatile(
        "{\n\t.reg .pred P;\n"
        "W_%=:\n\t"
        "mbarrier.try_wait.parity.acquire.cta.shared::cta.b64 P, [%0], %1, 0x989680;\n\t"
        "@P bra D_%=;\n\t"
        "bra W_%=;\n"
        "D_%=:\n\t}"
        :: "r"(mbar), "r"(parity) : "memory");
}

__global__ __launch_bounds__(THREADS, 1)
void addshift_kernel(const float* __restrict__ x,
                     const float* __restrict__ w1,
                     const float* __restrict__ w2,
                     const float* __restrict__ w3,
                     const int*   __restrict__ pad_hv,
                     const int*   __restrict__ idx_identit,
                     float* __restrict__ out)
{
    extern __shared__ float smem[];
    float4* tab = (float4*)(smem + OFF_TAB);   // [2][44]
    float*  wid = smem + OFF_WID;              // [2][12]
    int*    q   = (int*)(smem + OFF_Q);

    const int tid = threadIdx.x;
    const uint32_t smem_base = smem_u32(smem);
    const uint32_t fbar0 = smem_base + (uint32_t)OFF_BAR * 4u;        // full[s]
    const uint32_t ebar0 = fbar0 + 8u * NSLOT;                        // empty[s]

    // Zero data region once (guards stay zero; plane bytes overwritten by TMA).
    {
        float4* d = (float4*)smem;
        const float4 z = make_float4(0.f, 0.f, 0.f, 0.f);
        for (int i = tid; i < SM_DATA / 4; i += THREADS) d[i] = z;
    }
    if (tid == 0) {
        for (int s = 0; s < NSLOT; s++) {
            mbar_init(fbar0 + 8u * s, 1);
            mbar_init(ebar0 + 8u * s, NCW);
        }
    }
    __syncthreads();   // the only full-CTA barrier

    // ================= producer warp =================
    if (tid >= NCW * 32) {
        if (tid == NCW * 32) {
            asm volatile("fence.proxy.async.shared::cta;" ::: "memory");
            int pnk = 0, ptq = 0;
            for (int p = 0;; p++) {
                int s = p % NSLOT;
                if (p >= NSLOT)
                    mbar_wait(ebar0 + 8u * s, ((p - NSLOT) / NSLOT) & 1);
                if (pnk == 0) {
                    int t = atomicAdd(&g_tile_ctr, 1);
                    q[ptq & 3] = (t < NTILES) ? t : -1;
                }
                int t = q[ptq & 3];
                uint32_t bar = fbar0 + 8u * s;
                if (t < 0) {  // sentinel: flip full[s] so consumers see q=-1 and exit
                    asm volatile("mbarrier.arrive.shared.b64 _, [%0];" :: "r"(bar) : "memory");
                    break;
                }
                uint32_t dst = smem_base + (uint32_t)(GUARD + s * SLOT_STRIDE) * 4u;
                const float* src = x + (size_t)((t / C_OUT) * C_IN + (t % C_OUT) * NK + pnk) * PLANE;
                asm volatile("mbarrier.arrive.expect_tx.shared.b64 _, [%0], %1;"
                             :: "r"(bar), "r"((uint32_t)PLANE_BYTES) : "memory");
                asm volatile("cp.async.bulk.shared::cta.global.mbarrier::complete_tx::bytes "
                             "[%0], [%1], %2, [%3];"
                             :: "r"(dst), "l"(src), "r"((uint32_t)PLANE_BYTES), "r"(bar) : "memory");
                if (++pnk == NK) { pnk = 0; ptq++; }
            }
        }
        return;
    }

    // ================= compute warps =================
    const int w   = tid % WOUT;
    const int h0  = tid / WOUT;
    const int col = w + EP;
    const int rb0 = (h0 + EP) * HIN;
    const int vrow0 = h0 + EP;
    const bool k3 = (h0 < 8);
    const bool lane0 = ((tid & 31) == 0);

    int p = 0, tq = 0;
    for (;;) {
        int s = p % NSLOT;
        mbar_wait(fbar0 + 8u * s, (p / NSLOT) & 1);   // plane 0 ready; q visible
        const int t = q[tq & 3];
        if (t < 0) break;
        const int co = t % C_OUT, b = t / C_OUT, c0 = co * NK;

        // Double-buffered term tables for this tile.
        float4* tb = tab + (tq & 1) * 44;
        float*  wb = wid + (tq & 1) * 12;
        if (tid < 44) {
            int nk = tid >> 2, g = tid & 3, c = c0 + nk;
            float4 e;
            e.x = __int_as_float(pad_hv[c*8 + g]);
            e.y = w1[g*C_IN + c];
            e.z = __int_as_float(pad_hv[c*8 + 4 + g]);
            e.w = w2[g*C_IN + c];
            tb[tid] = e;
        }
        if (tid >= 64 && tid < 64 + NK) {
            int nk = tid - 64;
            float sw = 0.f;
            #pragma unroll
            for (int g = 0; g < 4; g++)
                if (idx_identit[co*4 + g] - c0 == nk) sw += w3[g*C_OUT + co];
            wb[nk] = sw;
        }
        asm volatile("bar.sync 1, %0;" :: "n"(NCW*32) : "memory");  // tables ready

        float acc_h[4] = {0.f,0.f,0.f,0.f};
        float acc_v[4] = {0.f,0.f,0.f,0.f};
        float acc_i[4] = {0.f,0.f,0.f,0.f};

        for (int nk = 0; nk < NK; nk++) {
            s = p % NSLOT;
            if (nk) mbar_wait(fbar0 + 8u * s, (p / NSLOT) & 1);
            const float* base = smem + GUARD + s * SLOT_STRIDE;
            const float* bh = base + rb0;
            const float* bv = base + col;

            #pragma unroll
            for (int g = 0; g < 4; g++) {
                float4 e = tb[nk*4 + g];
                int   sh = __float_as_int(e.x);
                float wh = e.y;
                int   sv = __float_as_int(e.z);
                float wv = e.w;

                int iw = col + sh;
                float wt = ((unsigned)iw < (unsigned)HIN) ? wh : 0.0f;
                const float* ph = bh + iw;                 // guards keep address safe
                acc_h[0] = fmaf(ph[0],         wt, acc_h[0]);
                acc_h[1] = fmaf(ph[ROWSTEP],   wt, acc_h[1]);
                acc_h[2] = fmaf(ph[2*ROWSTEP], wt, acc_h[2]);
                acc_h[3] = fmaf(ph[3*ROWSTEP], wt, acc_h[3]);   // k3 garbage unstored

                const float* pv = bv + (vrow0 + sv) * HIN; // OOB rows hit zero guards
                acc_v[0] = fmaf(pv[0],         wv, acc_v[0]);
                acc_v[1] = fmaf(pv[ROWSTEP],   wv, acc_v[1]);
                acc_v[2] = fmaf(pv[2*ROWSTEP], wv, acc_v[2]);
                acc_v[3] = fmaf(pv[3*ROWSTEP], wv, acc_v[3]);
            }

            float wi = wb[nk];
            if (wi != 0.0f) {      // warp-uniform branch
                const float* pi = bh + col;
                acc_i[0] = fmaf(pi[0],         wi, acc_i[0]);
                acc_i[1] = fmaf(pi[ROWSTEP],   wi, acc_i[1]);
                acc_i[2] = fmaf(pi[2*ROWSTEP], wi, acc_i[2]);
                acc_i[3] = fmaf(pi[3*ROWSTEP], wi, acc_i[3]);
            }

            // Warp is done with slot s. The 12 accumulator inputs force all of
            // this plane's LDS->FFMA chains to complete before the arrive issues,
            // so the producer can never overwrite data still being read.
            if (lane0) {
                asm volatile("mbarrier.arrive.release.cta.shared::cta.b64 _, [%0];"
                    :: "r"(ebar0 + 8u * s),
                       "f"(acc_h[0]), "f"(acc_h[1]), "f"(acc_h[2]), "f"(acc_h[3]),
                       "f"(acc_v[0]), "f"(acc_v[1]), "f"(acc_v[2]), "f"(acc_v[3]),
                       "f"(acc_i[0]), "f"(acc_i[1]), "f"(acc_i[2]), "f"(acc_i[3])
                    : "memory");
            }
            p++;
        }

        // Write outputs (coalesced: consecutive tid -> consecutive w).
        float* oh = out;
        float* ov = out + OUT_PLANE;
        float* oi = out + 2*OUT_PLANE;
        const size_t obase = ((size_t)(b * C_OUT + co)) * NPIX + (size_t)h0 * WOUT + w;
        #pragma unroll
        for (int k = 0; k < 3; k++) {
            size_t idx = obase + (size_t)(16*k) * WOUT;
            oh[idx] = acc_h[k];
            ov[idx] = acc_v[k];
            oi[idx] = acc_i[k];
        }
        if (k3) {
            size_t idx = obase + (size_t)48 * WOUT;
            oh[idx] = acc_h[3];
            ov[idx] = acc_v[3];
            oi[idx] = acc_i[3];
        }
        tq++;
    }
}

extern "C" void kernel_launch(void* const* d_in, const int* in_sizes, int n_in,
                              void* d_out, int out_size)
{
    const float* x           = (const float*)d_in[0];
    const float* w1          = (const float*)d_in[1];
    const float* w2          = (const float*)d_in[2];
    const float* w3          = (const float*)d_in[3];
    const int*   pad_hv      = (const int*)  d_in[4];
    const int*   idx_identit = (const int*)  d_in[5];
    float*       out         = (float*)d_out;

    cudaFuncSetAttribute(addshift_kernel,
                         cudaFuncAttributeMaxDynamicSharedMemorySize, SMEM_BYTES);

    reset_kernel<<<1, 32>>>();
    addshift_kernel<<<148, THREADS, SMEM_BYTES>>>(x, w1, w2, w3, pad_hv,
                                                  idx_identit, out);
}